// round 1
// baseline (speedup 1.0000x reference)
#include <cuda_runtime.h>
#include <math.h>

#define H_   16
#define D_   1024
#define HD_  64
#define PB_  512
#define B_   8
#define N_   512
#define BN_  (B_*N_)          // 4096
#define TWO_PB (2*PB_)        // 1024

// ---------------- scratch (static device arrays: no allocation allowed) ----
__device__ float g_q[B_*H_*N_*HD_];       // [B,H,N,HD]
__device__ float g_k[B_*H_*N_*HD_];
__device__ float g_v[B_*H_*N_*HD_];
__device__ float g_posk[H_*TWO_PB*HD_];   // [H,2PB,HD]
__device__ float g_posq[H_*TWO_PB*HD_];
__device__ float g_ctx[BN_*D_];           // [B,N,H,HD] == [4096,1024] row-major
__device__ float g_h[BN_*D_];             // pre-LN residual sum

// ---------------------------------------------------------------------------
// Generic NT GEMM: out[m,c] = sum_k A[m,k]*W[c,k] + bias[c]  (+ epilogue mode)
//   mode 0: pos proj   -> out[(h*2PB + m)*HD + hd],  c = h*64+hd
//   mode 1: qkv proj   -> out[((b*H+h)*N + n)*HD+hd], m = b*512+n
//   mode 2: out proj   -> out[m*D + c] = val + resid[m*D + c]
// 64x64 block tile, K-tile 32, 256 threads, 4x4 per thread.
// ---------------------------------------------------------------------------
__global__ __launch_bounds__(256) void gemm_nt(
    const float* __restrict__ A, const float* __restrict__ W,
    const float* __restrict__ bias, const float* __restrict__ resid,
    float* __restrict__ out, int K, int mode)
{
    __shared__ float As[64][33];
    __shared__ float Ws[64][33];
    const int bm = blockIdx.y * 64, bn = blockIdx.x * 64;
    const int tid = threadIdx.x, tx = tid & 15, ty = tid >> 4;

    float acc[4][4] = {};

    for (int k0 = 0; k0 < K; k0 += 32) {
        #pragma unroll
        for (int e = tid; e < 512; e += 256) {      // 512 float4 total (A+W interleaved by e)
            int r = e >> 3, k4 = (e & 7) * 4;
            float4 av = *(const float4*)&A[(size_t)(bm + r) * K + k0 + k4];
            As[r][k4 + 0] = av.x; As[r][k4 + 1] = av.y;
            As[r][k4 + 2] = av.z; As[r][k4 + 3] = av.w;
            float4 wv = *(const float4*)&W[(size_t)(bn + r) * K + k0 + k4];
            Ws[r][k4 + 0] = wv.x; Ws[r][k4 + 1] = wv.y;
            Ws[r][k4 + 2] = wv.z; Ws[r][k4 + 3] = wv.w;
        }
        __syncthreads();
        #pragma unroll
        for (int kk = 0; kk < 32; kk++) {
            float a[4], b[4];
            #pragma unroll
            for (int i = 0; i < 4; i++) { a[i] = As[ty*4 + i][kk]; b[i] = Ws[tx*4 + i][kk]; }
            #pragma unroll
            for (int ri = 0; ri < 4; ri++)
                #pragma unroll
                for (int ci = 0; ci < 4; ci++)
                    acc[ri][ci] += a[ri] * b[ci];
        }
        __syncthreads();
    }

    #pragma unroll
    for (int ri = 0; ri < 4; ri++) {
        int m = bm + ty*4 + ri;
        #pragma unroll
        for (int ci = 0; ci < 4; ci++) {
            int c = bn + tx*4 + ci;
            float val = acc[ri][ci] + bias[c];
            if (mode == 2) {
                out[(size_t)m * D_ + c] = val + resid[(size_t)m * D_ + c];
            } else if (mode == 1) {
                int b = m >> 9, n = m & 511, h = c >> 6, hd = c & 63;
                out[(((size_t)(b * H_ + h)) * N_ + n) * HD_ + hd] = val;
            } else {
                int h = c >> 6, hd = c & 63;
                out[((size_t)h * TWO_PB + m) * HD_ + hd] = val;
            }
        }
    }
}

// ---------------------------------------------------------------------------
// Fused disentangled attention (flash style).
// grid: (N/64, B*H). block: 256 threads. Dynamic smem.
// S[i,j] = (q_i.k_j + q_i.pk[i-j+PB] + k_j.pq[i-j+PB]) / sqrt(192)
// ---------------------------------------------------------------------------
#define ATTN_SMEM_FLOATS (3*64*65 + 2*127*65 + 64*65 + 3*64)
#define ATTN_SMEM_BYTES  (ATTN_SMEM_FLOATS * (int)sizeof(float))

__global__ __launch_bounds__(256) void attn_kernel(
    const float* __restrict__ q, const float* __restrict__ k,
    const float* __restrict__ v, const float* __restrict__ posk,
    const float* __restrict__ posq, float* __restrict__ ctx)
{
    extern __shared__ float sm[];
    float* Qs  = sm;                 // [64][65]
    float* Ks  = Qs  + 64*65;        // [64][65]
    float* Vs  = Ks  + 64*65;        // [64][65]
    float* PKs = Vs  + 64*65;        // [127][65]
    float* PQs = PKs + 127*65;       // [127][65]
    float* Ss  = PQs + 127*65;       // [64][65]
    float* mrow = Ss + 64*65;        // [64]
    float* lrow = mrow + 64;
    float* srow = lrow + 64;

    const int bh = blockIdx.y;
    const int b = bh / H_, h = bh % H_;
    const int i0 = blockIdx.x * 64;

    const float* qb  = q + ((size_t)bh * N_ + i0) * HD_;
    const float* kb  = k + (size_t)bh * N_ * HD_;
    const float* vb  = v + (size_t)bh * N_ * HD_;
    const float* pkb = posk + (size_t)h * TWO_PB * HD_;
    const float* pqb = posq + (size_t)h * TWO_PB * HD_;

    const int tid = threadIdx.x, tx = tid & 15, ty = tid >> 4;
    const int di0 = ty * 4, dj0 = tx * 4;
    const float inv_scale = 1.0f / sqrtf(192.0f);

    for (int e = tid; e < 64*64; e += 256) {
        int r = e >> 6, d = e & 63;
        Qs[r*65 + d] = qb[e];
    }
    if (tid < 64) { mrow[tid] = -INFINITY; lrow[tid] = 0.0f; }

    float ctxacc[4][4] = {};

    for (int j0 = 0; j0 < N_; j0 += 64) {
        for (int e = tid; e < 64*64; e += 256) {
            int r = e >> 6, d = e & 63;
            Ks[r*65 + d] = kb[(size_t)(j0 + r) * HD_ + d];
            Vs[r*65 + d] = vb[(size_t)(j0 + r) * HD_ + d];
        }
        const int base = i0 - j0 + PB_ - 63;   // window start; always in [1, 897]
        for (int e = tid; e < 127*64; e += 256) {
            int w = e >> 6, d = e & 63;
            PKs[w*65 + d] = pkb[(size_t)(base + w) * HD_ + d];
            PQs[w*65 + d] = pqb[(size_t)(base + w) * HD_ + d];
        }
        __syncthreads();

        // ---- scores 4x4 per thread ----
        float s[4][4] = {};
        const int wb = di0 - dj0 + 60;         // + (ri-ci+3) gives window row
        #pragma unroll 4
        for (int d = 0; d < 64; d++) {
            float qv[4], kv[4], pk7[7], pq7[7];
            #pragma unroll
            for (int i = 0; i < 4; i++) { qv[i] = Qs[(di0+i)*65 + d]; kv[i] = Ks[(dj0+i)*65 + d]; }
            #pragma unroll
            for (int t = 0; t < 7; t++) { pk7[t] = PKs[(wb+t)*65 + d]; pq7[t] = PQs[(wb+t)*65 + d]; }
            #pragma unroll
            for (int ri = 0; ri < 4; ri++)
                #pragma unroll
                for (int ci = 0; ci < 4; ci++) {
                    int t = ri - ci + 3;
                    s[ri][ci] += qv[ri] * (kv[ci] + pk7[t]) + kv[ci] * pq7[t];
                }
        }
        #pragma unroll
        for (int ri = 0; ri < 4; ri++)
            #pragma unroll
            for (int ci = 0; ci < 4; ci++)
                Ss[(di0+ri)*65 + dj0+ci] = s[ri][ci] * inv_scale;
        __syncthreads();

        // ---- online softmax: row max + rescale factor ----
        if (tid < 64) {
            float tm = -INFINITY;
            #pragma unroll 8
            for (int dj = 0; dj < 64; dj++) tm = fmaxf(tm, Ss[tid*65 + dj]);
            float mo = mrow[tid];
            float mn = fmaxf(mo, tm);
            mrow[tid] = mn;
            srow[tid] = __expf(mo - mn);   // 0 when mo == -inf
        }
        __syncthreads();

        // ---- p = exp(s - m); rescale ctx ----
        #pragma unroll
        for (int ri = 0; ri < 4; ri++) {
            float mr = mrow[di0 + ri];
            float sc = srow[di0 + ri];
            #pragma unroll
            for (int ci = 0; ci < 4; ci++) {
                float p = __expf(Ss[(di0+ri)*65 + dj0+ci] - mr);
                Ss[(di0+ri)*65 + dj0+ci] = p;
                ctxacc[ri][ci] *= sc;
            }
        }
        __syncthreads();

        // ---- l update (read-only on Ss, concurrent with PV) ----
        if (tid < 64) {
            float sum = 0.0f;
            #pragma unroll 8
            for (int dj = 0; dj < 64; dj++) sum += Ss[tid*65 + dj];
            lrow[tid] = lrow[tid] * srow[tid] + sum;
        }

        // ---- ctx += P @ V ----
        #pragma unroll 4
        for (int dj = 0; dj < 64; dj++) {
            float pv[4], vv[4];
            #pragma unroll
            for (int ri = 0; ri < 4; ri++) pv[ri] = Ss[(di0+ri)*65 + dj];
            #pragma unroll
            for (int ci = 0; ci < 4; ci++) vv[ci] = Vs[dj*65 + tx*4 + ci];
            #pragma unroll
            for (int ri = 0; ri < 4; ri++)
                #pragma unroll
                for (int ci = 0; ci < 4; ci++)
                    ctxacc[ri][ci] += pv[ri] * vv[ci];
        }
        __syncthreads();
    }

    // ---- epilogue: divide by l, write ctx as [B,N,H,HD] ----
    #pragma unroll
    for (int ri = 0; ri < 4; ri++) {
        float invl = 1.0f / lrow[di0 + ri];
        int irow = i0 + di0 + ri;
        #pragma unroll
        for (int ci = 0; ci < 4; ci++) {
            ctx[(((size_t)b * N_ + irow) * H_ + h) * HD_ + tx*4 + ci] = ctxacc[ri][ci] * invl;
        }
    }
}

// ---------------------------------------------------------------------------
// Row LayerNorm: out = (h - mu)/sqrt(var+eps)*g + b, one block per row
// ---------------------------------------------------------------------------
__global__ __launch_bounds__(256) void ln_kernel(
    const float* __restrict__ hb, const float* __restrict__ gam,
    const float* __restrict__ bet, float* __restrict__ out)
{
    const int row = blockIdx.x, tid = threadIdx.x;
    const float* hr = hb + (size_t)row * D_;
    __shared__ float red[256];

    float lv[4];
    float s = 0.0f;
    #pragma unroll
    for (int i = 0; i < 4; i++) { lv[i] = hr[i*256 + tid]; s += lv[i]; }
    red[tid] = s; __syncthreads();
    #pragma unroll
    for (int o = 128; o > 0; o >>= 1) { if (tid < o) red[tid] += red[tid + o]; __syncthreads(); }
    float mu = red[0] * (1.0f / 1024.0f);
    __syncthreads();

    float s2 = 0.0f;
    #pragma unroll
    for (int i = 0; i < 4; i++) { float dv = lv[i] - mu; s2 += dv * dv; }
    red[tid] = s2; __syncthreads();
    #pragma unroll
    for (int o = 128; o > 0; o >>= 1) { if (tid < o) red[tid] += red[tid + o]; __syncthreads(); }
    float var = red[0] * (1.0f / 1024.0f);
    float inv = rsqrtf(var + 1e-7f);

    #pragma unroll
    for (int i = 0; i < 4; i++) {
        int c = i*256 + tid;
        out[(size_t)row * D_ + c] = (lv[i] - mu) * inv * gam[c] + bet[c];
    }
}

// ---------------------------------------------------------------------------
extern "C" void kernel_launch(void* const* d_in, const int* in_sizes, int n_in,
                              void* d_out, int out_size)
{
    const float* hidden = (const float*)d_in[0];
    const float* rel    = (const float*)d_in[1];
    const float* q_w = (const float*)d_in[2];  const float* q_b = (const float*)d_in[3];
    const float* k_w = (const float*)d_in[4];  const float* k_b = (const float*)d_in[5];
    const float* v_w = (const float*)d_in[6];  const float* v_b = (const float*)d_in[7];
    const float* pk_w = (const float*)d_in[8]; const float* pk_b = (const float*)d_in[9];
    const float* pq_w = (const float*)d_in[10];const float* pq_b = (const float*)d_in[11];
    const float* o_w = (const float*)d_in[12]; const float* o_b = (const float*)d_in[13];
    const float* ln_g = (const float*)d_in[14];const float* ln_b = (const float*)d_in[15];

    float *pq_, *pk_, *pv_, *ppk, *ppq, *pctx, *ph;
    cudaGetSymbolAddress((void**)&pq_,  g_q);
    cudaGetSymbolAddress((void**)&pk_,  g_k);
    cudaGetSymbolAddress((void**)&pv_,  g_v);
    cudaGetSymbolAddress((void**)&ppk,  g_posk);
    cudaGetSymbolAddress((void**)&ppq,  g_posq);
    cudaGetSymbolAddress((void**)&pctx, g_ctx);
    cudaGetSymbolAddress((void**)&ph,   g_h);

    // Q, K, V projections: [4096,1024] x [1024,1024]^T
    dim3 gqkv(D_/64, BN_/64);
    gemm_nt<<<gqkv, 256>>>(hidden, q_w, q_b, nullptr, pq_, D_, 1);
    gemm_nt<<<gqkv, 256>>>(hidden, k_w, k_b, nullptr, pk_, D_, 1);
    gemm_nt<<<gqkv, 256>>>(hidden, v_w, v_b, nullptr, pv_, D_, 1);

    // pos_k, pos_q projections: [1024,1024] x [1024,1024]^T
    dim3 gpos(D_/64, TWO_PB/64);
    gemm_nt<<<gpos, 256>>>(rel, pk_w, pk_b, nullptr, ppk, D_, 0);
    gemm_nt<<<gpos, 256>>>(rel, pq_w, pq_b, nullptr, ppq, D_, 0);

    // fused disentangled attention
    cudaFuncSetAttribute(attn_kernel, cudaFuncAttributeMaxDynamicSharedMemorySize,
                         ATTN_SMEM_BYTES);
    attn_kernel<<<dim3(N_/64, B_*H_), 256, ATTN_SMEM_BYTES>>>(pq_, pk_, pv_, ppk, ppq, pctx);

    // output projection + bias + residual
    gemm_nt<<<gqkv, 256>>>(pctx, o_w, o_b, hidden, ph, D_, 2);

    // layernorm -> final output
    ln_kernel<<<BN_, 256>>>(ph, ln_g, ln_b, (float*)d_out);
}

// round 4
// speedup vs baseline: 1.8627x; 1.8627x over previous
#include <cuda_runtime.h>
#include <cuda_bf16.h>
#include <math.h>
#include <stdint.h>

#define H_   16
#define D_   1024
#define HD_  64
#define PB_  512
#define B_   8
#define N_   512
#define BN_  (B_*N_)          // 4096
#define TWO_PB (2*PB_)        // 1024

// ---------------- scratch (static device arrays: no allocation allowed) ----
__device__ float g_q[B_*H_*N_*HD_];       // [B,H,N,HD]
__device__ float g_k[B_*H_*N_*HD_];
__device__ float g_v[B_*H_*N_*HD_];
__device__ float g_posk[H_*TWO_PB*HD_];   // [H,2PB,HD]
__device__ float g_posq[H_*TWO_PB*HD_];
__device__ float g_ctx[BN_*D_];           // [B,N,H,HD] == [4096,1024] row-major
__device__ float g_h[BN_*D_];             // pre-LN residual sum

__device__ __align__(16) __nv_bfloat16 g_hid_bf[BN_*D_];
__device__ __align__(16) __nv_bfloat16 g_rel_bf[TWO_PB*D_];
__device__ __align__(16) __nv_bfloat16 g_ctx_bf[BN_*D_];
__device__ __align__(16) __nv_bfloat16 g_wbf[6][D_*D_];   // q,k,v,pk,pq,o

// ============================================================
// helpers (baseline sm_80+ features only: ldmatrix, mma.sync, cp.async)
// ============================================================
__device__ __forceinline__ uint32_t smem_u32(const void* p) {
    uint32_t a;
    asm("{ .reg .u64 t; cvta.to.shared.u64 t, %1; cvt.u32.u64 %0, t; }"
        : "=r"(a) : "l"(p));
    return a;
}
__device__ __forceinline__ void ldsm_x4(uint32_t* r, uint32_t addr) {
    asm volatile("ldmatrix.sync.aligned.m8n8.x4.shared.b16 {%0,%1,%2,%3}, [%4];"
        : "=r"(r[0]), "=r"(r[1]), "=r"(r[2]), "=r"(r[3]) : "r"(addr));
}
__device__ __forceinline__ void mma16816(float* c, const uint32_t* a, uint32_t b0, uint32_t b1) {
    asm volatile("mma.sync.aligned.m16n8k16.row.col.f32.bf16.bf16.f32 "
        "{%0,%1,%2,%3}, {%4,%5,%6,%7}, {%8,%9}, {%0,%1,%2,%3};"
        : "+f"(c[0]), "+f"(c[1]), "+f"(c[2]), "+f"(c[3])
        : "r"(a[0]), "r"(a[1]), "r"(a[2]), "r"(a[3]), "r"(b0), "r"(b1));
}
#define CP_ASYNC16(dst, src) \
    asm volatile("cp.async.cg.shared.global [%0], [%1], 16;" :: "r"(dst), "l"(src))
#define CP_COMMIT() asm volatile("cp.async.commit_group;" ::: "memory")
#define CP_WAIT0()  asm volatile("cp.async.wait_group 0;" ::: "memory")
#define CP_WAIT1()  asm volatile("cp.async.wait_group 1;" ::: "memory")

#define SWZ(off) ((off) ^ (((off) >> 3) & 0x70))

// ============================================================
// fp32 -> bf16 conversion (vectorized, 4 elems/thread)
// ============================================================
__global__ __launch_bounds__(256) void f2bf(const float* __restrict__ in,
                                            __nv_bfloat16* __restrict__ out, int n) {
    int i = (blockIdx.x * 256 + threadIdx.x) * 4;
    if (i < n) {
        float4 v = *(const float4*)(in + i);
        __nv_bfloat162 lo = __floats2bfloat162_rn(v.x, v.y);
        __nv_bfloat162 hi = __floats2bfloat162_rn(v.z, v.w);
        *(uint2*)(out + i) = make_uint2(*(uint32_t*)&lo, *(uint32_t*)&hi);
    }
}

// ============================================================
// mma.sync bf16 NT GEMM: out[m,c] = sum_k A[m,k]*W[c,k] + bias[c]
// CTA tile 128x128, K-tile 64, double-buffered cp.async.
// 8 warps in 4(m) x 2(n); warp tile 32x64 = 2x8 m16n8k16 tiles.
// mode 0: pos reshape, mode 1: qkv reshape, mode 2: +residual flat
// ============================================================
#define KT 64
#define ABYTES (128*128)            // 128 rows x 128B (64 bf16)
#define TILEBUF (2*ABYTES)          // A + B per stage = 32KB
#define GEMM_SMEM (2*TILEBUF)       // double buffer = 64KB

__global__ __launch_bounds__(256) void gemm_mma(
    const __nv_bfloat16* __restrict__ A, const __nv_bfloat16* __restrict__ W,
    const float* __restrict__ bias, const float* __restrict__ resid,
    float* __restrict__ out, int mode)
{
    extern __shared__ char smch[];
    const uint32_t sbase = smem_u32(smch);
    const int tid = threadIdx.x, warp = tid >> 5, lane = tid & 31;
    const int bm = blockIdx.y * 128, bn = blockIdx.x * 128;
    const int wm = (warp >> 1) * 32, wn = (warp & 1) * 64;

    float acc[2][8][4];
    #pragma unroll
    for (int i = 0; i < 2; i++)
        #pragma unroll
        for (int j = 0; j < 8; j++)
            #pragma unroll
            for (int l = 0; l < 4; l++) acc[i][j][l] = 0.0f;

    // ---- tile loader: 1024 16B chunks each for A and B ----
    auto load_tile = [&](int kt, int bsel) {
        const __nv_bfloat16* Ap = A + (size_t)bm * D_ + kt * KT;
        const __nv_bfloat16* Wp = W + (size_t)bn * D_ + kt * KT;
        uint32_t da = sbase + bsel * TILEBUF;
        uint32_t db = da + ABYTES;
        #pragma unroll
        for (int i = 0; i < 4; i++) {
            int c = i * 256 + tid;            // 0..1023
            int r = c >> 3, k8 = c & 7;
            uint32_t off = SWZ((uint32_t)(r * 128 + k8 * 16));
            CP_ASYNC16(da + off, Ap + (size_t)r * D_ + k8 * 8);
            CP_ASYNC16(db + off, Wp + (size_t)r * D_ + k8 * 8);
        }
    };

    load_tile(0, 0);
    CP_COMMIT();

    const int matm = lane >> 3, rin = lane & 7;   // ldmatrix lane roles
    int buf = 0;
    for (int kt = 0; kt < 16; kt++) {
        if (kt < 15) { load_tile(kt + 1, buf ^ 1); CP_COMMIT(); CP_WAIT1(); }
        else CP_WAIT0();
        __syncthreads();

        uint32_t abase = sbase + buf * TILEBUF;
        uint32_t bbase = abase + ABYTES;
        #pragma unroll
        for (int ks = 0; ks < 4; ks++) {
            uint32_t af[2][4], bfr[4][4];
            int kcol = ks * 16 + (matm >> 1) * 8;   // k col for this lane's matrix
            #pragma unroll
            for (int mt = 0; mt < 2; mt++) {
                int m = wm + mt * 16 + (matm & 1) * 8 + rin;
                uint32_t off = SWZ((uint32_t)(m * 128 + kcol * 2));
                ldsm_x4(af[mt], abase + off);
            }
            #pragma unroll
            for (int u = 0; u < 4; u++) {
                int n = wn + u * 16 + (matm & 1) * 8 + rin;
                uint32_t off = SWZ((uint32_t)(n * 128 + kcol * 2));
                ldsm_x4(bfr[u], bbase + off);
            }
            #pragma unroll
            for (int mt = 0; mt < 2; mt++)
                #pragma unroll
                for (int nt = 0; nt < 8; nt++) {
                    int u = nt >> 1, w = nt & 1;
                    mma16816(acc[mt][nt], af[mt], bfr[u][w], bfr[u][w + 2]);
                }
        }
        __syncthreads();
        buf ^= 1;
    }

    // ---- epilogue: c0,c1 @ (row g, col tg*2..+1); c2,c3 @ (row g+8) ----
    const int g = lane >> 2, tg = lane & 3;
    #pragma unroll
    for (int mt = 0; mt < 2; mt++) {
        #pragma unroll
        for (int nt = 0; nt < 8; nt++) {
            int col = bn + wn + nt * 8 + tg * 2;
            float b0 = bias[col], b1 = bias[col + 1];
            #pragma unroll
            for (int half = 0; half < 2; half++) {
                int m = bm + wm + mt * 16 + g + half * 8;
                float v0 = acc[mt][nt][half * 2 + 0] + b0;
                float v1 = acc[mt][nt][half * 2 + 1] + b1;
                if (mode == 2) {
                    size_t idx = (size_t)m * D_ + col;
                    float2 r = *(const float2*)&resid[idx];
                    *(float2*)&out[idx] = make_float2(v0 + r.x, v1 + r.y);
                } else if (mode == 1) {
                    int bb = m >> 9, n = m & 511, h = col >> 6, hd = col & 63;
                    size_t idx = (((size_t)(bb * H_ + h)) * N_ + n) * HD_ + hd;
                    *(float2*)&out[idx] = make_float2(v0, v1);
                } else {
                    int h = col >> 6, hd = col & 63;
                    size_t idx = ((size_t)h * TWO_PB + m) * HD_ + hd;
                    *(float2*)&out[idx] = make_float2(v0, v1);
                }
            }
        }
    }
}

// ---------------------------------------------------------------------------
// Fused disentangled attention (flash style, SIMT fp32).
// S[i,j] = (q_i.k_j + q_i.pk[i-j+PB] + k_j.pq[i-j+PB]) / sqrt(192)
// ---------------------------------------------------------------------------
#define ATTN_SMEM_FLOATS (3*64*65 + 2*127*65 + 64*65 + 3*64)
#define ATTN_SMEM_BYTES  (ATTN_SMEM_FLOATS * (int)sizeof(float))

__global__ __launch_bounds__(256) void attn_kernel(
    const float* __restrict__ q, const float* __restrict__ k,
    const float* __restrict__ v, const float* __restrict__ posk,
    const float* __restrict__ posq, float* __restrict__ ctx)
{
    extern __shared__ float sm[];
    float* Qs  = sm;                 // [64][65]
    float* Ks  = Qs  + 64*65;
    float* Vs  = Ks  + 64*65;
    float* PKs = Vs  + 64*65;        // [127][65]
    float* PQs = PKs + 127*65;
    float* Ss  = PQs + 127*65;       // [64][65]
    float* mrow = Ss + 64*65;
    float* lrow = mrow + 64;
    float* srow = lrow + 64;

    const int bh = blockIdx.y;
    const int b = bh / H_, h = bh % H_;
    const int i0 = blockIdx.x * 64;

    const float* qb  = q + ((size_t)bh * N_ + i0) * HD_;
    const float* kb  = k + (size_t)bh * N_ * HD_;
    const float* vb  = v + (size_t)bh * N_ * HD_;
    const float* pkb = posk + (size_t)h * TWO_PB * HD_;
    const float* pqb = posq + (size_t)h * TWO_PB * HD_;

    const int tid = threadIdx.x, tx = tid & 15, ty = tid >> 4;
    const int di0 = ty * 4, dj0 = tx * 4;
    const float inv_scale = 1.0f / sqrtf(192.0f);

    for (int e = tid; e < 64*64; e += 256) {
        int r = e >> 6, d = e & 63;
        Qs[r*65 + d] = qb[e];
    }
    if (tid < 64) { mrow[tid] = -INFINITY; lrow[tid] = 0.0f; }

    float ctxacc[4][4] = {};

    for (int j0 = 0; j0 < N_; j0 += 64) {
        for (int e = tid; e < 64*64; e += 256) {
            int r = e >> 6, d = e & 63;
            Ks[r*65 + d] = kb[(size_t)(j0 + r) * HD_ + d];
            Vs[r*65 + d] = vb[(size_t)(j0 + r) * HD_ + d];
        }
        const int base = i0 - j0 + PB_ - 63;
        for (int e = tid; e < 127*64; e += 256) {
            int w = e >> 6, d = e & 63;
            PKs[w*65 + d] = pkb[(size_t)(base + w) * HD_ + d];
            PQs[w*65 + d] = pqb[(size_t)(base + w) * HD_ + d];
        }
        __syncthreads();

        float s[4][4] = {};
        const int wb = di0 - dj0 + 60;
        #pragma unroll 4
        for (int d = 0; d < 64; d++) {
            float qv[4], kv[4], pk7[7], pq7[7];
            #pragma unroll
            for (int i = 0; i < 4; i++) { qv[i] = Qs[(di0+i)*65 + d]; kv[i] = Ks[(dj0+i)*65 + d]; }
            #pragma unroll
            for (int t = 0; t < 7; t++) { pk7[t] = PKs[(wb+t)*65 + d]; pq7[t] = PQs[(wb+t)*65 + d]; }
            #pragma unroll
            for (int ri = 0; ri < 4; ri++)
                #pragma unroll
                for (int ci = 0; ci < 4; ci++) {
                    int t = ri - ci + 3;
                    s[ri][ci] += qv[ri] * (kv[ci] + pk7[t]) + kv[ci] * pq7[t];
                }
        }
        #pragma unroll
        for (int ri = 0; ri < 4; ri++)
            #pragma unroll
            for (int ci = 0; ci < 4; ci++)
                Ss[(di0+ri)*65 + dj0+ci] = s[ri][ci] * inv_scale;
        __syncthreads();

        if (tid < 64) {
            float tm = -INFINITY;
            #pragma unroll 8
            for (int dj = 0; dj < 64; dj++) tm = fmaxf(tm, Ss[tid*65 + dj]);
            float mo = mrow[tid];
            float mn = fmaxf(mo, tm);
            mrow[tid] = mn;
            srow[tid] = __expf(mo - mn);
        }
        __syncthreads();

        #pragma unroll
        for (int ri = 0; ri < 4; ri++) {
            float mr = mrow[di0 + ri];
            float sc = srow[di0 + ri];
            #pragma unroll
            for (int ci = 0; ci < 4; ci++) {
                float p = __expf(Ss[(di0+ri)*65 + dj0+ci] - mr);
                Ss[(di0+ri)*65 + dj0+ci] = p;
                ctxacc[ri][ci] *= sc;
            }
        }
        __syncthreads();

        if (tid < 64) {
            float sum = 0.0f;
            #pragma unroll 8
            for (int dj = 0; dj < 64; dj++) sum += Ss[tid*65 + dj];
            lrow[tid] = lrow[tid] * srow[tid] + sum;
        }

        #pragma unroll 4
        for (int dj = 0; dj < 64; dj++) {
            float pv[4], vv[4];
            #pragma unroll
            for (int ri = 0; ri < 4; ri++) pv[ri] = Ss[(di0+ri)*65 + dj];
            #pragma unroll
            for (int ci = 0; ci < 4; ci++) vv[ci] = Vs[dj*65 + tx*4 + ci];
            #pragma unroll
            for (int ri = 0; ri < 4; ri++)
                #pragma unroll
                for (int ci = 0; ci < 4; ci++)
                    ctxacc[ri][ci] += pv[ri] * vv[ci];
        }
        __syncthreads();
    }

    #pragma unroll
    for (int ri = 0; ri < 4; ri++) {
        float invl = 1.0f / lrow[di0 + ri];
        int irow = i0 + di0 + ri;
        #pragma unroll
        for (int ci = 0; ci < 4; ci++) {
            ctx[(((size_t)b * N_ + irow) * H_ + h) * HD_ + tx*4 + ci] = ctxacc[ri][ci] * invl;
        }
    }
}

// ---------------------------------------------------------------------------
// Row LayerNorm
// ---------------------------------------------------------------------------
__global__ __launch_bounds__(256) void ln_kernel(
    const float* __restrict__ hb, const float* __restrict__ gam,
    const float* __restrict__ bet, float* __restrict__ out)
{
    const int row = blockIdx.x, tid = threadIdx.x;
    const float* hr = hb + (size_t)row * D_;
    __shared__ float red[256];

    float lv[4];
    float s = 0.0f;
    #pragma unroll
    for (int i = 0; i < 4; i++) { lv[i] = hr[i*256 + tid]; s += lv[i]; }
    red[tid] = s; __syncthreads();
    #pragma unroll
    for (int o = 128; o > 0; o >>= 1) { if (tid < o) red[tid] += red[tid + o]; __syncthreads(); }
    float mu = red[0] * (1.0f / 1024.0f);
    __syncthreads();

    float s2 = 0.0f;
    #pragma unroll
    for (int i = 0; i < 4; i++) { float dv = lv[i] - mu; s2 += dv * dv; }
    red[tid] = s2; __syncthreads();
    #pragma unroll
    for (int o = 128; o > 0; o >>= 1) { if (tid < o) red[tid] += red[tid + o]; __syncthreads(); }
    float var = red[0] * (1.0f / 1024.0f);
    float inv = rsqrtf(var + 1e-7f);

    #pragma unroll
    for (int i = 0; i < 4; i++) {
        int c = i*256 + tid;
        out[(size_t)row * D_ + c] = (lv[i] - mu) * inv * gam[c] + bet[c];
    }
}

// ---------------------------------------------------------------------------
extern "C" void kernel_launch(void* const* d_in, const int* in_sizes, int n_in,
                              void* d_out, int out_size)
{
    const float* hidden = (const float*)d_in[0];
    const float* rel    = (const float*)d_in[1];
    const float* q_w = (const float*)d_in[2];  const float* q_b = (const float*)d_in[3];
    const float* k_w = (const float*)d_in[4];  const float* k_b = (const float*)d_in[5];
    const float* v_w = (const float*)d_in[6];  const float* v_b = (const float*)d_in[7];
    const float* pk_w = (const float*)d_in[8]; const float* pk_b = (const float*)d_in[9];
    const float* pq_w = (const float*)d_in[10];const float* pq_b = (const float*)d_in[11];
    const float* o_w = (const float*)d_in[12]; const float* o_b = (const float*)d_in[13];
    const float* ln_g = (const float*)d_in[14];const float* ln_b = (const float*)d_in[15];

    float *pq_, *pk_, *pv_, *ppk, *ppq, *pctx, *ph;
    __nv_bfloat16 *phidbf, *prelbf, *pctxbf, *pwbf;
    cudaGetSymbolAddress((void**)&pq_,  g_q);
    cudaGetSymbolAddress((void**)&pk_,  g_k);
    cudaGetSymbolAddress((void**)&pv_,  g_v);
    cudaGetSymbolAddress((void**)&ppk,  g_posk);
    cudaGetSymbolAddress((void**)&ppq,  g_posq);
    cudaGetSymbolAddress((void**)&pctx, g_ctx);
    cudaGetSymbolAddress((void**)&ph,   g_h);
    cudaGetSymbolAddress((void**)&phidbf, g_hid_bf);
    cudaGetSymbolAddress((void**)&prelbf, g_rel_bf);
    cudaGetSymbolAddress((void**)&pctxbf, g_ctx_bf);
    cudaGetSymbolAddress((void**)&pwbf,   g_wbf);

    __nv_bfloat16* wq  = pwbf + 0ull * D_ * D_;
    __nv_bfloat16* wk  = pwbf + 1ull * D_ * D_;
    __nv_bfloat16* wv  = pwbf + 2ull * D_ * D_;
    __nv_bfloat16* wpk = pwbf + 3ull * D_ * D_;
    __nv_bfloat16* wpq = pwbf + 4ull * D_ * D_;
    __nv_bfloat16* wo  = pwbf + 5ull * D_ * D_;

    cudaFuncSetAttribute(gemm_mma, cudaFuncAttributeMaxDynamicSharedMemorySize, GEMM_SMEM);
    cudaFuncSetAttribute(attn_kernel, cudaFuncAttributeMaxDynamicSharedMemorySize,
                         ATTN_SMEM_BYTES);

    // fp32 -> bf16 conversions
    f2bf<<<BN_*D_/1024, 256>>>(hidden, phidbf, BN_*D_);
    f2bf<<<TWO_PB*D_/1024, 256>>>(rel, prelbf, TWO_PB*D_);
    f2bf<<<D_*D_/1024, 256>>>(q_w, wq, D_*D_);
    f2bf<<<D_*D_/1024, 256>>>(k_w, wk, D_*D_);
    f2bf<<<D_*D_/1024, 256>>>(v_w, wv, D_*D_);
    f2bf<<<D_*D_/1024, 256>>>(pk_w, wpk, D_*D_);
    f2bf<<<D_*D_/1024, 256>>>(pq_w, wpq, D_*D_);
    f2bf<<<D_*D_/1024, 256>>>(o_w, wo, D_*D_);

    // tensor-core (mma.sync) projections
    dim3 gqkv(D_/128, BN_/128);      // (8, 32)
    dim3 gpos(D_/128, TWO_PB/128);   // (8, 8)
    gemm_mma<<<gqkv, 256, GEMM_SMEM>>>(phidbf, wq, q_b, nullptr, pq_, 1);
    gemm_mma<<<gqkv, 256, GEMM_SMEM>>>(phidbf, wk, k_b, nullptr, pk_, 1);
    gemm_mma<<<gqkv, 256, GEMM_SMEM>>>(phidbf, wv, v_b, nullptr, pv_, 1);
    gemm_mma<<<gpos, 256, GEMM_SMEM>>>(prelbf, wpk, pk_b, nullptr, ppk, 0);
    gemm_mma<<<gpos, 256, GEMM_SMEM>>>(prelbf, wpq, pq_b, nullptr, ppq, 0);

    // fused disentangled attention (fp32 SIMT)
    attn_kernel<<<dim3(N_/64, B_*H_), 256, ATTN_SMEM_BYTES>>>(pq_, pk_, pv_, ppk, ppq, pctx);

    // output projection + bias + residual (mma.sync)
    f2bf<<<BN_*D_/1024, 256>>>(pctx, pctxbf, BN_*D_);
    gemm_mma<<<gqkv, 256, GEMM_SMEM>>>(pctxbf, wo, o_b, hidden, ph, 2);

    // layernorm -> final output
    ln_kernel<<<BN_, 256>>>(ph, ln_g, ln_b, (float*)d_out);
}

// round 6
// speedup vs baseline: 6.4816x; 3.4796x over previous
#include <cuda_runtime.h>
#include <cuda_bf16.h>
#include <math.h>
#include <stdint.h>

#define H_   16
#define D_   1024
#define HD_  64
#define PB_  512
#define B_   8
#define N_   512
#define BN_  (B_*N_)          // 4096
#define TWO_PB (2*PB_)        // 1024

// ---------------- scratch (static device arrays: no allocation allowed) ----
__device__ __align__(16) __nv_bfloat16 g_qb[B_*H_*N_*HD_];     // [B,H,N,HD]
__device__ __align__(16) __nv_bfloat16 g_kb[B_*H_*N_*HD_];
__device__ __align__(16) __nv_bfloat16 g_vb[B_*H_*N_*HD_];
__device__ __align__(16) __nv_bfloat16 g_pkb[H_*TWO_PB*HD_];   // [H,2PB,HD]
__device__ __align__(16) __nv_bfloat16 g_pqb[H_*TWO_PB*HD_];
__device__ __align__(16) __nv_bfloat16 g_ctx_bf[BN_*D_];       // [B,N,H,HD]
__device__ float g_h[BN_*D_];                                  // pre-LN residual sum

__device__ __align__(16) __nv_bfloat16 g_hid_bf[BN_*D_];
__device__ __align__(16) __nv_bfloat16 g_rel_bf[TWO_PB*D_];
__device__ __align__(16) __nv_bfloat16 g_wbf[6][D_*D_];        // q,k,v,pk,pq,o

// ============================================================
// helpers (baseline sm_80+: ldmatrix, mma.sync, cp.async)
// ============================================================
__device__ __forceinline__ uint32_t smem_u32(const void* p) {
    uint32_t a;
    asm("{ .reg .u64 t; cvta.to.shared.u64 t, %1; cvt.u32.u64 %0, t; }"
        : "=r"(a) : "l"(p));
    return a;
}
__device__ __forceinline__ void ldsm_x4(uint32_t* r, uint32_t addr) {
    asm volatile("ldmatrix.sync.aligned.m8n8.x4.shared.b16 {%0,%1,%2,%3}, [%4];"
        : "=r"(r[0]), "=r"(r[1]), "=r"(r[2]), "=r"(r[3]) : "r"(addr));
}
__device__ __forceinline__ void ldsm_x4_t(uint32_t* r, uint32_t addr) {
    asm volatile("ldmatrix.sync.aligned.m8n8.x4.trans.shared.b16 {%0,%1,%2,%3}, [%4];"
        : "=r"(r[0]), "=r"(r[1]), "=r"(r[2]), "=r"(r[3]) : "r"(addr));
}
__device__ __forceinline__ void mma16816(float* c, const uint32_t* a, uint32_t b0, uint32_t b1) {
    asm volatile("mma.sync.aligned.m16n8k16.row.col.f32.bf16.bf16.f32 "
        "{%0,%1,%2,%3}, {%4,%5,%6,%7}, {%8,%9}, {%0,%1,%2,%3};"
        : "+f"(c[0]), "+f"(c[1]), "+f"(c[2]), "+f"(c[3])
        : "r"(a[0]), "r"(a[1]), "r"(a[2]), "r"(a[3]), "r"(b0), "r"(b1));
}
#define CP_ASYNC16(dst, src) \
    asm volatile("cp.async.cg.shared.global [%0], [%1], 16;" :: "r"(dst), "l"(src))
#define CP_COMMIT() asm volatile("cp.async.commit_group;" ::: "memory")
#define CP_WAIT0()  asm volatile("cp.async.wait_group 0;" ::: "memory")
#define CP_WAIT1()  asm volatile("cp.async.wait_group 1;" ::: "memory")

#define SWZ(off) ((off) ^ (((off) >> 3) & 0x70))

// ============================================================
// fp32 -> bf16 conversion kernels
// ============================================================
__global__ __launch_bounds__(256) void f2bf(const float* __restrict__ in,
                                            __nv_bfloat16* __restrict__ out, int n) {
    int i = (blockIdx.x * 256 + threadIdx.x) * 4;
    if (i < n) {
        float4 v = *(const float4*)(in + i);
        __nv_bfloat162 lo = __floats2bfloat162_rn(v.x, v.y);
        __nv_bfloat162 hi = __floats2bfloat162_rn(v.z, v.w);
        *(uint2*)(out + i) = make_uint2(*(uint32_t*)&lo, *(uint32_t*)&hi);
    }
}
// six D*D weight tensors in one launch (blockIdx.y selects)
__global__ __launch_bounds__(256) void f2bf6(
    const float* __restrict__ p0, const float* __restrict__ p1,
    const float* __restrict__ p2, const float* __restrict__ p3,
    const float* __restrict__ p4, const float* __restrict__ p5,
    __nv_bfloat16* __restrict__ out)
{
    const float* ps[6] = {p0, p1, p2, p3, p4, p5};
    const float* in = ps[blockIdx.y];
    int i = (blockIdx.x * 256 + threadIdx.x) * 4;
    float4 v = *(const float4*)(in + i);
    __nv_bfloat162 lo = __floats2bfloat162_rn(v.x, v.y);
    __nv_bfloat162 hi = __floats2bfloat162_rn(v.z, v.w);
    *(uint2*)(out + (size_t)blockIdx.y * D_ * D_ + i) = make_uint2(*(uint32_t*)&lo, *(uint32_t*)&hi);
}

// ============================================================
// mma.sync bf16 NT GEMM: out[m,c] = sum_k A[m,k]*W[c,k] + bias[c]
// CTA tile 128x128, K-tile 64, double-buffered cp.async.
// mode 0: pos reshape (bf16 out), mode 1: qkv reshape (bf16 out),
// mode 2: +residual flat (fp32 out)
// ============================================================
#define KT 64
#define ABYTES (128*128)
#define TILEBUF (2*ABYTES)
#define GEMM_SMEM (2*TILEBUF)

__global__ __launch_bounds__(256) void gemm_mma(
    const __nv_bfloat16* __restrict__ A, const __nv_bfloat16* __restrict__ W,
    const float* __restrict__ bias, const float* __restrict__ resid,
    void* __restrict__ outv, int mode)
{
    extern __shared__ char smch[];
    const uint32_t sbase = smem_u32(smch);
    const int tid = threadIdx.x, warp = tid >> 5, lane = tid & 31;
    const int bm = blockIdx.y * 128, bn = blockIdx.x * 128;
    const int wm = (warp >> 1) * 32, wn = (warp & 1) * 64;

    float acc[2][8][4];
    #pragma unroll
    for (int i = 0; i < 2; i++)
        #pragma unroll
        for (int j = 0; j < 8; j++)
            #pragma unroll
            for (int l = 0; l < 4; l++) acc[i][j][l] = 0.0f;

    auto load_tile = [&](int kt, int bsel) {
        const __nv_bfloat16* Ap = A + (size_t)bm * D_ + kt * KT;
        const __nv_bfloat16* Wp = W + (size_t)bn * D_ + kt * KT;
        uint32_t da = sbase + bsel * TILEBUF;
        uint32_t db = da + ABYTES;
        #pragma unroll
        for (int i = 0; i < 4; i++) {
            int c = i * 256 + tid;
            int r = c >> 3, k8 = c & 7;
            uint32_t off = SWZ((uint32_t)(r * 128 + k8 * 16));
            CP_ASYNC16(da + off, Ap + (size_t)r * D_ + k8 * 8);
            CP_ASYNC16(db + off, Wp + (size_t)r * D_ + k8 * 8);
        }
    };

    load_tile(0, 0);
    CP_COMMIT();

    const int matm = lane >> 3, rin = lane & 7;
    int buf = 0;
    for (int kt = 0; kt < 16; kt++) {
        if (kt < 15) { load_tile(kt + 1, buf ^ 1); CP_COMMIT(); CP_WAIT1(); }
        else CP_WAIT0();
        __syncthreads();

        uint32_t abase = sbase + buf * TILEBUF;
        uint32_t bbase = abase + ABYTES;
        #pragma unroll
        for (int ks = 0; ks < 4; ks++) {
            uint32_t af[2][4], bfr[4][4];
            int kcol = ks * 16 + (matm >> 1) * 8;
            #pragma unroll
            for (int mt = 0; mt < 2; mt++) {
                int m = wm + mt * 16 + (matm & 1) * 8 + rin;
                ldsm_x4(af[mt], abase + SWZ((uint32_t)(m * 128 + kcol * 2)));
            }
            #pragma unroll
            for (int u = 0; u < 4; u++) {
                int n = wn + u * 16 + (matm & 1) * 8 + rin;
                ldsm_x4(bfr[u], bbase + SWZ((uint32_t)(n * 128 + kcol * 2)));
            }
            #pragma unroll
            for (int mt = 0; mt < 2; mt++)
                #pragma unroll
                for (int nt = 0; nt < 8; nt++) {
                    int u = nt >> 1, w = nt & 1;
                    mma16816(acc[mt][nt], af[mt], bfr[u][w], bfr[u][w + 2]);
                }
        }
        __syncthreads();
        buf ^= 1;
    }

    const int g = lane >> 2, tg = lane & 3;
    #pragma unroll
    for (int mt = 0; mt < 2; mt++) {
        #pragma unroll
        for (int nt = 0; nt < 8; nt++) {
            int col = bn + wn + nt * 8 + tg * 2;
            float b0 = bias[col], b1 = bias[col + 1];
            #pragma unroll
            for (int half = 0; half < 2; half++) {
                int m = bm + wm + mt * 16 + g + half * 8;
                float v0 = acc[mt][nt][half * 2 + 0] + b0;
                float v1 = acc[mt][nt][half * 2 + 1] + b1;
                if (mode == 2) {
                    float* out = (float*)outv;
                    size_t idx = (size_t)m * D_ + col;
                    float2 r = *(const float2*)&resid[idx];
                    *(float2*)&out[idx] = make_float2(v0 + r.x, v1 + r.y);
                } else {
                    __nv_bfloat16* out = (__nv_bfloat16*)outv;
                    __nv_bfloat162 pk2 = __floats2bfloat162_rn(v0, v1);
                    size_t idx;
                    if (mode == 1) {
                        int bb = m >> 9, n = m & 511, h = col >> 6, hd = col & 63;
                        idx = (((size_t)(bb * H_ + h)) * N_ + n) * HD_ + hd;
                    } else {
                        int h = col >> 6, hd = col & 63;
                        idx = ((size_t)h * TWO_PB + m) * HD_ + hd;
                    }
                    *(__nv_bfloat162*)&out[idx] = pk2;
                }
            }
        }
    }
}

// ============================================================
// Tensorized disentangled flash attention.
// grid (N/64, B*H), 128 threads (4 warps, warp w owns rows w*16..+15).
// S[i,j] = (q_i.k_j + q_i.pk[i-j+PB] + k_j.pq[i-j+PB]) / sqrt(192)
// Band trick: within a 64x64 tile, i-j+PB spans a 127-row window of pk/pq.
// ============================================================
#define BAND_STRIDE 264                       // bytes per row of band buffers
#define AT_SQ   0
#define AT_SK   8192
#define AT_SV   16384
#define AT_SPK  24576
#define AT_SPQ  40960
#define AT_SC   57344                          // C2P band, bf16 [64][128], stride 264
#define AT_SP   (AT_SC + 64*BAND_STRIDE)       // P2C band
#define AT_SMEM (AT_SP + 64*BAND_STRIDE)       // = 91136 bytes

__global__ __launch_bounds__(128) void attn_mma(
    const __nv_bfloat16* __restrict__ q, const __nv_bfloat16* __restrict__ k,
    const __nv_bfloat16* __restrict__ v, const __nv_bfloat16* __restrict__ posk,
    const __nv_bfloat16* __restrict__ posq, __nv_bfloat16* __restrict__ ctx)
{
    extern __shared__ char smch[];
    const uint32_t sb = smem_u32(smch);
    const uint32_t sQ = sb + AT_SQ, sK = sb + AT_SK, sV = sb + AT_SV;
    const uint32_t sPK = sb + AT_SPK, sPQ = sb + AT_SPQ;
    const uint32_t sC = sb + AT_SC, sP = sb + AT_SP;

    const int tid = threadIdx.x, warp = tid >> 5, lane = tid & 31;
    const int g = lane >> 2, tg = lane & 3;
    const int matm = lane >> 3, rin = lane & 7;
    const int wm = warp * 16;
    const int i0 = blockIdx.x * 64;
    const int bh = blockIdx.y;
    const int h = bh & (H_ - 1);

    const __nv_bfloat16* qb  = q + ((size_t)bh * N_ + i0) * HD_;
    const __nv_bfloat16* kb  = k + (size_t)bh * N_ * HD_;
    const __nv_bfloat16* vb  = v + (size_t)bh * N_ * HD_;
    const __nv_bfloat16* pkb = posk + (size_t)h * TWO_PB * HD_;
    const __nv_bfloat16* pqb = posq + (size_t)h * TWO_PB * HD_;

    // load Q tile (64 rows x 128B, SW128)
    #pragma unroll
    for (int it = 0; it < 4; it++) {
        int c = it * 128 + tid, r = c >> 3, k8 = c & 7;
        CP_ASYNC16(sQ + SWZ((uint32_t)(r * 128 + k8 * 16)), qb + r * HD_ + k8 * 8);
    }
    CP_COMMIT();

    float m0 = -INFINITY, m1 = -INFINITY, l0 = 0.f, l1 = 0.f;
    float opv[8][4];
    #pragma unroll
    for (int i = 0; i < 8; i++)
        #pragma unroll
        for (int e = 0; e < 4; e++) opv[i][e] = 0.f;
    const float inv_scale = 0.0721687836f;     // 1/sqrt(192)

    for (int j0 = 0; j0 < N_; j0 += 64) {
        const int base = i0 - j0 + PB_ - 63;   // in [1, 897]
        #pragma unroll
        for (int it = 0; it < 4; it++) {
            int c = it * 128 + tid, r = c >> 3, k8 = c & 7;
            uint32_t off = SWZ((uint32_t)(r * 128 + k8 * 16));
            CP_ASYNC16(sK + off, kb + (size_t)(j0 + r) * HD_ + k8 * 8);
            CP_ASYNC16(sV + off, vb + (size_t)(j0 + r) * HD_ + k8 * 8);
        }
        #pragma unroll
        for (int it = 0; it < 8; it++) {
            int c = it * 128 + tid, r = c >> 3, k8 = c & 7;
            int sr = base + r; if (sr > 1023) sr = 1023;   // row 127 is unused pad
            uint32_t off = SWZ((uint32_t)(r * 128 + k8 * 16));
            CP_ASYNC16(sPK + off, pkb + (size_t)sr * HD_ + k8 * 8);
            CP_ASYNC16(sPQ + off, pqb + (size_t)sr * HD_ + k8 * 8);
        }
        CP_COMMIT(); CP_WAIT0(); __syncthreads();

        // ---- phase 1: band GEMMs C2P = Q.PKwin^T, P2C = K.PQwin^T (n=128) ----
        #pragma unroll
        for (int ph = 0; ph < 2; ph++) {
            uint32_t aSrc = ph ? sK : sQ;
            uint32_t bSrc = ph ? sPQ : sPK;
            uint32_t dSt  = ph ? sP : sC;
            float t[16][4];
            #pragma unroll
            for (int i = 0; i < 16; i++)
                #pragma unroll
                for (int e = 0; e < 4; e++) t[i][e] = 0.f;
            #pragma unroll
            for (int ks = 0; ks < 4; ks++) {
                uint32_t af[4];
                int ar = wm + (matm & 1) * 8 + rin, kc = ks * 16 + (matm >> 1) * 8;
                ldsm_x4(af, aSrc + SWZ((uint32_t)(ar * 128 + kc * 2)));
                #pragma unroll
                for (int u = 0; u < 8; u++) {
                    uint32_t bf4[4];
                    int nr = u * 16 + (matm & 1) * 8 + rin;
                    ldsm_x4(bf4, bSrc + SWZ((uint32_t)(nr * 128 + kc * 2)));
                    mma16816(t[2 * u],     af, bf4[0], bf4[2]);
                    mma16816(t[2 * u + 1], af, bf4[1], bf4[3]);
                }
            }
            #pragma unroll
            for (int nt = 0; nt < 16; nt++) {
                int col = nt * 8 + tg * 2;
                __nv_bfloat162 lo = __floats2bfloat162_rn(t[nt][0], t[nt][1]);
                __nv_bfloat162 hi = __floats2bfloat162_rn(t[nt][2], t[nt][3]);
                uint32_t a0 = dSt + (wm + g) * BAND_STRIDE + col * 2;
                uint32_t a1 = dSt + (wm + g + 8) * BAND_STRIDE + col * 2;
                asm volatile("st.shared.b32 [%0], %1;" :: "r"(a0), "r"(*(uint32_t*)&lo));
                asm volatile("st.shared.b32 [%0], %1;" :: "r"(a1), "r"(*(uint32_t*)&hi));
            }
        }
        __syncthreads();

        // ---- phase 2: S = Q.K^T, gather band terms, online softmax ----
        float s[8][4];
        #pragma unroll
        for (int i = 0; i < 8; i++)
            #pragma unroll
            for (int e = 0; e < 4; e++) s[i][e] = 0.f;
        #pragma unroll
        for (int ks = 0; ks < 4; ks++) {
            uint32_t af[4];
            int ar = wm + (matm & 1) * 8 + rin, kc = ks * 16 + (matm >> 1) * 8;
            ldsm_x4(af, sQ + SWZ((uint32_t)(ar * 128 + kc * 2)));
            #pragma unroll
            for (int u = 0; u < 4; u++) {
                uint32_t bf4[4];
                int nr = u * 16 + (matm & 1) * 8 + rin;
                ldsm_x4(bf4, sK + SWZ((uint32_t)(nr * 128 + kc * 2)));
                mma16816(s[2 * u],     af, bf4[0], bf4[2]);
                mma16816(s[2 * u + 1], af, bf4[1], bf4[3]);
            }
        }
        #pragma unroll
        for (int nt = 0; nt < 8; nt++) {
            #pragma unroll
            for (int e = 0; e < 4; e++) {
                int di = wm + g + (e >> 1) * 8;
                int dj = nt * 8 + tg * 2 + (e & 1);
                int w = di - dj + 63;
                uint16_t cv, pv2;
                asm volatile("ld.shared.u16 %0, [%1];" : "=h"(cv)
                             : "r"(sC + di * BAND_STRIDE + w * 2));
                asm volatile("ld.shared.u16 %0, [%1];" : "=h"(pv2)
                             : "r"(sP + dj * BAND_STRIDE + w * 2));
                float add = __bfloat162float(*(__nv_bfloat16*)&cv)
                          + __bfloat162float(*(__nv_bfloat16*)&pv2);
                s[nt][e] = (s[nt][e] + add) * inv_scale;
            }
        }
        // row max (rows wm+g and wm+g+8)
        float mx0 = -INFINITY, mx1 = -INFINITY;
        #pragma unroll
        for (int nt = 0; nt < 8; nt++) {
            mx0 = fmaxf(mx0, fmaxf(s[nt][0], s[nt][1]));
            mx1 = fmaxf(mx1, fmaxf(s[nt][2], s[nt][3]));
        }
        mx0 = fmaxf(mx0, __shfl_xor_sync(0xFFFFFFFF, mx0, 1));
        mx0 = fmaxf(mx0, __shfl_xor_sync(0xFFFFFFFF, mx0, 2));
        mx1 = fmaxf(mx1, __shfl_xor_sync(0xFFFFFFFF, mx1, 1));
        mx1 = fmaxf(mx1, __shfl_xor_sync(0xFFFFFFFF, mx1, 2));
        float mn0 = fmaxf(m0, mx0), mn1 = fmaxf(m1, mx1);
        float sc0 = __expf(m0 - mn0), sc1 = __expf(m1 - mn1);
        m0 = mn0; m1 = mn1;
        float sum0 = 0.f, sum1 = 0.f;
        #pragma unroll
        for (int nt = 0; nt < 8; nt++) {
            #pragma unroll
            for (int e = 0; e < 4; e++) {
                float p = __expf(s[nt][e] - ((e < 2) ? mn0 : mn1));
                s[nt][e] = p;
                if (e < 2) sum0 += p; else sum1 += p;
            }
        }
        sum0 += __shfl_xor_sync(0xFFFFFFFF, sum0, 1);
        sum0 += __shfl_xor_sync(0xFFFFFFFF, sum0, 2);
        sum1 += __shfl_xor_sync(0xFFFFFFFF, sum1, 1);
        sum1 += __shfl_xor_sync(0xFFFFFFFF, sum1, 2);
        l0 = l0 * sc0 + sum0;
        l1 = l1 * sc1 + sum1;
        #pragma unroll
        for (int nt = 0; nt < 8; nt++) {
            opv[nt][0] *= sc0; opv[nt][1] *= sc0;
            opv[nt][2] *= sc1; opv[nt][3] *= sc1;
        }
        // ---- PV: P (bf16 fragments from s) @ V via ldmatrix.trans ----
        #pragma unroll
        for (int kk = 0; kk < 4; kk++) {
            uint32_t aP[4];
            __nv_bfloat162 t0 = __floats2bfloat162_rn(s[2*kk][0],   s[2*kk][1]);
            __nv_bfloat162 t1 = __floats2bfloat162_rn(s[2*kk][2],   s[2*kk][3]);
            __nv_bfloat162 t2 = __floats2bfloat162_rn(s[2*kk+1][0], s[2*kk+1][1]);
            __nv_bfloat162 t3 = __floats2bfloat162_rn(s[2*kk+1][2], s[2*kk+1][3]);
            aP[0] = *(uint32_t*)&t0; aP[1] = *(uint32_t*)&t1;
            aP[2] = *(uint32_t*)&t2; aP[3] = *(uint32_t*)&t3;
            int jb = kk * 16;
            #pragma unroll
            for (int du = 0; du < 4; du++) {
                uint32_t bv[4];
                int vr = jb + (matm & 1) * 8 + rin, vc = du * 16 + (matm >> 1) * 8;
                ldsm_x4_t(bv, sV + SWZ((uint32_t)(vr * 128 + vc * 2)));
                mma16816(opv[2 * du],     aP, bv[0], bv[1]);
                mma16816(opv[2 * du + 1], aP, bv[2], bv[3]);
            }
        }
        __syncthreads();
    }

    // epilogue: normalize and write bf16 ctx [B,N,H,HD]
    const int b = bh >> 4;
    float il0 = 1.0f / l0, il1 = 1.0f / l1;
    int row0 = i0 + wm + g, row1 = row0 + 8;
    #pragma unroll
    for (int nt = 0; nt < 8; nt++) {
        int d = nt * 8 + tg * 2;
        __nv_bfloat162 o0 = __floats2bfloat162_rn(opv[nt][0] * il0, opv[nt][1] * il0);
        __nv_bfloat162 o1 = __floats2bfloat162_rn(opv[nt][2] * il1, opv[nt][3] * il1);
        *(__nv_bfloat162*)&ctx[(((size_t)b * N_ + row0) * H_ + h) * HD_ + d] = o0;
        *(__nv_bfloat162*)&ctx[(((size_t)b * N_ + row1) * H_ + h) * HD_ + d] = o1;
    }
}

// ---------------------------------------------------------------------------
// Row LayerNorm
// ---------------------------------------------------------------------------
__global__ __launch_bounds__(256) void ln_kernel(
    const float* __restrict__ hb, const float* __restrict__ gam,
    const float* __restrict__ bet, float* __restrict__ out)
{
    const int row = blockIdx.x, tid = threadIdx.x;
    const float* hr = hb + (size_t)row * D_;
    __shared__ float red[256];

    float lv[4];
    float s = 0.0f;
    #pragma unroll
    for (int i = 0; i < 4; i++) { lv[i] = hr[i*256 + tid]; s += lv[i]; }
    red[tid] = s; __syncthreads();
    #pragma unroll
    for (int o = 128; o > 0; o >>= 1) { if (tid < o) red[tid] += red[tid + o]; __syncthreads(); }
    float mu = red[0] * (1.0f / 1024.0f);
    __syncthreads();

    float s2 = 0.0f;
    #pragma unroll
    for (int i = 0; i < 4; i++) { float dv = lv[i] - mu; s2 += dv * dv; }
    red[tid] = s2; __syncthreads();
    #pragma unroll
    for (int o = 128; o > 0; o >>= 1) { if (tid < o) red[tid] += red[tid + o]; __syncthreads(); }
    float var = red[0] * (1.0f / 1024.0f);
    float inv = rsqrtf(var + 1e-7f);

    #pragma unroll
    for (int i = 0; i < 4; i++) {
        int c = i*256 + tid;
        out[(size_t)row * D_ + c] = (lv[i] - mu) * inv * gam[c] + bet[c];
    }
}

// ---------------------------------------------------------------------------
extern "C" void kernel_launch(void* const* d_in, const int* in_sizes, int n_in,
                              void* d_out, int out_size)
{
    const float* hidden = (const float*)d_in[0];
    const float* rel    = (const float*)d_in[1];
    const float* q_w = (const float*)d_in[2];  const float* q_b = (const float*)d_in[3];
    const float* k_w = (const float*)d_in[4];  const float* k_b = (const float*)d_in[5];
    const float* v_w = (const float*)d_in[6];  const float* v_b = (const float*)d_in[7];
    const float* pk_w = (const float*)d_in[8]; const float* pk_b = (const float*)d_in[9];
    const float* pq_w = (const float*)d_in[10];const float* pq_b = (const float*)d_in[11];
    const float* o_w = (const float*)d_in[12]; const float* o_b = (const float*)d_in[13];
    const float* ln_g = (const float*)d_in[14];const float* ln_b = (const float*)d_in[15];

    __nv_bfloat16 *pqb, *pkb, *pvb, *ppk, *ppq, *pctxbf, *phidbf, *prelbf, *pwbf;
    float *ph;
    cudaGetSymbolAddress((void**)&pqb,  g_qb);
    cudaGetSymbolAddress((void**)&pkb,  g_kb);
    cudaGetSymbolAddress((void**)&pvb,  g_vb);
    cudaGetSymbolAddress((void**)&ppk,  g_pkb);
    cudaGetSymbolAddress((void**)&ppq,  g_pqb);
    cudaGetSymbolAddress((void**)&pctxbf, g_ctx_bf);
    cudaGetSymbolAddress((void**)&ph,   g_h);
    cudaGetSymbolAddress((void**)&phidbf, g_hid_bf);
    cudaGetSymbolAddress((void**)&prelbf, g_rel_bf);
    cudaGetSymbolAddress((void**)&pwbf,   g_wbf);

    __nv_bfloat16* wq  = pwbf + 0ull * D_ * D_;
    __nv_bfloat16* wk  = pwbf + 1ull * D_ * D_;
    __nv_bfloat16* wv  = pwbf + 2ull * D_ * D_;
    __nv_bfloat16* wpk = pwbf + 3ull * D_ * D_;
    __nv_bfloat16* wpq = pwbf + 4ull * D_ * D_;
    __nv_bfloat16* wo  = pwbf + 5ull * D_ * D_;

    cudaFuncSetAttribute(gemm_mma, cudaFuncAttributeMaxDynamicSharedMemorySize, GEMM_SMEM);
    cudaFuncSetAttribute(attn_mma, cudaFuncAttributeMaxDynamicSharedMemorySize, AT_SMEM);

    // fp32 -> bf16 conversions
    f2bf<<<BN_*D_/1024, 256>>>(hidden, phidbf, BN_*D_);
    f2bf<<<TWO_PB*D_/1024, 256>>>(rel, prelbf, TWO_PB*D_);
    f2bf6<<<dim3(D_*D_/1024, 6), 256>>>(q_w, k_w, v_w, pk_w, pq_w, o_w, pwbf);

    // tensor-core (mma.sync) projections -> bf16 q/k/v/pos
    dim3 gqkv(D_/128, BN_/128);      // (8, 32)
    dim3 gpos(D_/128, TWO_PB/128);   // (8, 8)
    gemm_mma<<<gqkv, 256, GEMM_SMEM>>>(phidbf, wq, q_b, nullptr, pqb, 1);
    gemm_mma<<<gqkv, 256, GEMM_SMEM>>>(phidbf, wk, k_b, nullptr, pkb, 1);
    gemm_mma<<<gqkv, 256, GEMM_SMEM>>>(phidbf, wv, v_b, nullptr, pvb, 1);
    gemm_mma<<<gpos, 256, GEMM_SMEM>>>(prelbf, wpk, pk_b, nullptr, ppk, 0);
    gemm_mma<<<gpos, 256, GEMM_SMEM>>>(prelbf, wpq, pq_b, nullptr, ppq, 0);

    // tensorized disentangled flash attention -> bf16 ctx
    attn_mma<<<dim3(N_/64, B_*H_), 128, AT_SMEM>>>(pqb, pkb, pvb, ppk, ppq, pctxbf);

    // output projection + bias + residual (fp32 out)
    gemm_mma<<<gqkv, 256, GEMM_SMEM>>>(pctxbf, wo, o_b, hidden, ph, 2);

    // layernorm -> final output
    ln_kernel<<<BN_, 256>>>(ph, ln_g, ln_b, (float*)d_out);
}

// round 8
// speedup vs baseline: 7.0655x; 1.0901x over previous
#include <cuda_runtime.h>
#include <cuda_bf16.h>
#include <math.h>
#include <stdint.h>

#define H_   16
#define D_   1024
#define HD_  64
#define PB_  512
#define B_   8
#define N_   512
#define BN_  (B_*N_)          // 4096
#define TWO_PB (2*PB_)        // 1024

// ---------------- scratch (static device arrays: no allocation allowed) ----
__device__ __align__(16) __nv_bfloat16 g_qb[B_*H_*N_*HD_];     // [B,H,N,HD]
__device__ __align__(16) __nv_bfloat16 g_kb[B_*H_*N_*HD_];
__device__ __align__(16) __nv_bfloat16 g_vb[B_*H_*N_*HD_];
__device__ __align__(16) __nv_bfloat16 g_pkb[H_*TWO_PB*HD_];   // [H,2PB,HD]
__device__ __align__(16) __nv_bfloat16 g_pqb[H_*TWO_PB*HD_];
__device__ __align__(16) __nv_bfloat16 g_ctx_bf[BN_*D_];       // [B,N,H,HD]
__device__ float g_h[BN_*D_];                                  // pre-LN residual sum

__device__ __align__(16) __nv_bfloat16 g_hid_bf[BN_*D_];
__device__ __align__(16) __nv_bfloat16 g_rel_bf[TWO_PB*D_];
__device__ __align__(16) __nv_bfloat16 g_wbf[6][D_*D_];        // q,k,v,pk,pq,o (contiguous)

// ============================================================
// helpers (baseline sm_80+: ldmatrix, mma.sync, cp.async)
// ============================================================
__device__ __forceinline__ uint32_t smem_u32(const void* p) {
    uint32_t a;
    asm("{ .reg .u64 t; cvta.to.shared.u64 t, %1; cvt.u32.u64 %0, t; }"
        : "=r"(a) : "l"(p));
    return a;
}
__device__ __forceinline__ void ldsm_x4(uint32_t* r, uint32_t addr) {
    asm volatile("ldmatrix.sync.aligned.m8n8.x4.shared.b16 {%0,%1,%2,%3}, [%4];"
        : "=r"(r[0]), "=r"(r[1]), "=r"(r[2]), "=r"(r[3]) : "r"(addr));
}
__device__ __forceinline__ void ldsm_x4_t(uint32_t* r, uint32_t addr) {
    asm volatile("ldmatrix.sync.aligned.m8n8.x4.trans.shared.b16 {%0,%1,%2,%3}, [%4];"
        : "=r"(r[0]), "=r"(r[1]), "=r"(r[2]), "=r"(r[3]) : "r"(addr));
}
__device__ __forceinline__ void mma16816(float* c, const uint32_t* a, uint32_t b0, uint32_t b1) {
    asm volatile("mma.sync.aligned.m16n8k16.row.col.f32.bf16.bf16.f32 "
        "{%0,%1,%2,%3}, {%4,%5,%6,%7}, {%8,%9}, {%0,%1,%2,%3};"
        : "+f"(c[0]), "+f"(c[1]), "+f"(c[2]), "+f"(c[3])
        : "r"(a[0]), "r"(a[1]), "r"(a[2]), "r"(a[3]), "r"(b0), "r"(b1));
}
#define CP_ASYNC16(dst, src) \
    asm volatile("cp.async.cg.shared.global [%0], [%1], 16;" :: "r"(dst), "l"(src))
#define CP_COMMIT() asm volatile("cp.async.commit_group;" ::: "memory")
#define CP_WAIT0()  asm volatile("cp.async.wait_group 0;" ::: "memory")
#define CP_WAIT1()  asm volatile("cp.async.wait_group 1;" ::: "memory")

#define SWZ(off) ((off) ^ (((off) >> 3) & 0x70))

// ============================================================
// fp32 -> bf16 conversion kernels
// ============================================================
__global__ __launch_bounds__(256) void f2bf(const float* __restrict__ in,
                                            __nv_bfloat16* __restrict__ out, int n) {
    int i = (blockIdx.x * 256 + threadIdx.x) * 4;
    if (i < n) {
        float4 v = *(const float4*)(in + i);
        __nv_bfloat162 lo = __floats2bfloat162_rn(v.x, v.y);
        __nv_bfloat162 hi = __floats2bfloat162_rn(v.z, v.w);
        *(uint2*)(out + i) = make_uint2(*(uint32_t*)&lo, *(uint32_t*)&hi);
    }
}
__global__ __launch_bounds__(256) void f2bf6(
    const float* __restrict__ p0, const float* __restrict__ p1,
    const float* __restrict__ p2, const float* __restrict__ p3,
    const float* __restrict__ p4, const float* __restrict__ p5,
    __nv_bfloat16* __restrict__ out)
{
    const float* ps[6] = {p0, p1, p2, p3, p4, p5};
    const float* in = ps[blockIdx.y];
    int i = (blockIdx.x * 256 + threadIdx.x) * 4;
    float4 v = *(const float4*)(in + i);
    __nv_bfloat162 lo = __floats2bfloat162_rn(v.x, v.y);
    __nv_bfloat162 hi = __floats2bfloat162_rn(v.z, v.w);
    *(uint2*)(out + (size_t)blockIdx.y * D_ * D_ + i) = make_uint2(*(uint32_t*)&lo, *(uint32_t*)&hi);
}

// ============================================================
// mma.sync bf16 NT GEMM, 3-stage cp.async pipeline.
// out[m,c] = sum_k A[m,k]*W[c,k] + bias[c]; CTA tile 128x128, K-tile 64.
// mode 1: fused QKV (W rows [0,3072), t=bn>>10 selects g_qb/g_kb/g_vb + bias)
// mode 0: fused pos (W rows [0,2048), t selects g_pkb/g_pqb)
// mode 2: O proj + residual (fp32 out)
// ============================================================
#define KT 64
#define ABYTES (128*128)
#define STAGEBUF (2*ABYTES)          // A + B per stage = 32KB
#define GEMM_SMEM (3*STAGEBUF)       // 96KB

__global__ __launch_bounds__(256) void gemm_mma(
    const __nv_bfloat16* __restrict__ A, const __nv_bfloat16* __restrict__ W,
    const float* __restrict__ b0p, const float* __restrict__ b1p,
    const float* __restrict__ b2p, const float* __restrict__ resid,
    float* __restrict__ outf, int mode)
{
    extern __shared__ char smch[];
    const uint32_t sbase = smem_u32(smch);
    const int tid = threadIdx.x, warp = tid >> 5, lane = tid & 31;
    const int bm = blockIdx.y * 128, bn = blockIdx.x * 128;
    const int wm = (warp >> 1) * 32, wn = (warp & 1) * 64;

    float acc[2][8][4];
    #pragma unroll
    for (int i = 0; i < 2; i++)
        #pragma unroll
        for (int j = 0; j < 8; j++)
            #pragma unroll
            for (int l = 0; l < 4; l++) acc[i][j][l] = 0.0f;

    auto load_tile = [&](int kt, int stage) {
        const __nv_bfloat16* Ap = A + (size_t)bm * D_ + kt * KT;
        const __nv_bfloat16* Wp = W + (size_t)bn * D_ + kt * KT;
        uint32_t da = sbase + stage * STAGEBUF;
        uint32_t db = da + ABYTES;
        #pragma unroll
        for (int i = 0; i < 4; i++) {
            int c = i * 256 + tid;
            int r = c >> 3, k8 = c & 7;
            uint32_t off = SWZ((uint32_t)(r * 128 + k8 * 16));
            CP_ASYNC16(da + off, Ap + (size_t)r * D_ + k8 * 8);
            CP_ASYNC16(db + off, Wp + (size_t)r * D_ + k8 * 8);
        }
    };

    load_tile(0, 0); CP_COMMIT();
    load_tile(1, 1); CP_COMMIT();

    const int matm = lane >> 3, rin = lane & 7;
    int stage = 0;
    for (int kt = 0; kt < 16; kt++) {
        if (kt == 15) CP_WAIT0(); else CP_WAIT1();
        __syncthreads();
        if (kt + 2 < 16) {
            int ns = stage + 2; if (ns >= 3) ns -= 3;
            load_tile(kt + 2, ns);
            CP_COMMIT();
        }
        uint32_t abase = sbase + stage * STAGEBUF;
        uint32_t bbase = abase + ABYTES;
        #pragma unroll
        for (int ks = 0; ks < 4; ks++) {
            uint32_t af[2][4], bfr[4][4];
            int kcol = ks * 16 + (matm >> 1) * 8;
            #pragma unroll
            for (int mt = 0; mt < 2; mt++) {
                int m = wm + mt * 16 + (matm & 1) * 8 + rin;
                ldsm_x4(af[mt], abase + SWZ((uint32_t)(m * 128 + kcol * 2)));
            }
            #pragma unroll
            for (int u = 0; u < 4; u++) {
                int n = wn + u * 16 + (matm & 1) * 8 + rin;
                ldsm_x4(bfr[u], bbase + SWZ((uint32_t)(n * 128 + kcol * 2)));
            }
            #pragma unroll
            for (int mt = 0; mt < 2; mt++)
                #pragma unroll
                for (int nt = 0; nt < 8; nt++) {
                    int u = nt >> 1, w = nt & 1;
                    mma16816(acc[mt][nt], af[mt], bfr[u][w], bfr[u][w + 2]);
                }
        }
        stage++; if (stage >= 3) stage -= 3;
    }

    // ---- epilogue ----
    const int g = lane >> 2, tg = lane & 3;
    const int t = bn >> 10;                         // which tensor (fused modes)
    const float* bias = (t == 0) ? b0p : ((t == 1) ? b1p : b2p);
    __nv_bfloat16* outbf = nullptr;
    if (mode == 1) outbf = (t == 0) ? g_qb : ((t == 1) ? g_kb : g_vb);
    else if (mode == 0) outbf = (t == 0) ? g_pkb : g_pqb;

    #pragma unroll
    for (int mt = 0; mt < 2; mt++) {
        #pragma unroll
        for (int nt = 0; nt < 8; nt++) {
            int col = bn + wn + nt * 8 + tg * 2;     // global col in fused N
            int cn = col & 1023;                      // col within tensor
            float bb0 = bias[cn], bb1 = bias[cn + 1];
            #pragma unroll
            for (int half = 0; half < 2; half++) {
                int m = bm + wm + mt * 16 + g + half * 8;
                float v0 = acc[mt][nt][half * 2 + 0] + bb0;
                float v1 = acc[mt][nt][half * 2 + 1] + bb1;
                if (mode == 2) {
                    size_t idx = (size_t)m * D_ + cn;
                    float2 r = *(const float2*)&resid[idx];
                    *(float2*)&outf[idx] = make_float2(v0 + r.x, v1 + r.y);
                } else {
                    __nv_bfloat162 pk2 = __floats2bfloat162_rn(v0, v1);
                    size_t idx;
                    int h = cn >> 6, hd = cn & 63;
                    if (mode == 1) {
                        int bb = m >> 9, n = m & 511;
                        idx = (((size_t)(bb * H_ + h)) * N_ + n) * HD_ + hd;
                    } else {
                        idx = ((size_t)h * TWO_PB + m) * HD_ + hd;
                    }
                    *(__nv_bfloat162*)&outbf[idx] = pk2;
                }
            }
        }
    }
}

// ============================================================
// Tensorized disentangled flash attention (unchanged from R6 pass).
// grid (N/64, B*H), 128 threads (4 warps, warp w owns rows w*16..+15).
// S[i,j] = (q_i.k_j + q_i.pk[i-j+PB] + k_j.pq[i-j+PB]) / sqrt(192)
// ============================================================
#define BAND_STRIDE 264
#define AT_SQ   0
#define AT_SK   8192
#define AT_SV   16384
#define AT_SPK  24576
#define AT_SPQ  40960
#define AT_SC   57344
#define AT_SP   (AT_SC + 64*BAND_STRIDE)
#define AT_SMEM (AT_SP + 64*BAND_STRIDE)

__global__ __launch_bounds__(128) void attn_mma(
    const __nv_bfloat16* __restrict__ q, const __nv_bfloat16* __restrict__ k,
    const __nv_bfloat16* __restrict__ v, const __nv_bfloat16* __restrict__ posk,
    const __nv_bfloat16* __restrict__ posq, __nv_bfloat16* __restrict__ ctx)
{
    extern __shared__ char smch[];
    const uint32_t sb = smem_u32(smch);
    const uint32_t sQ = sb + AT_SQ, sK = sb + AT_SK, sV = sb + AT_SV;
    const uint32_t sPK = sb + AT_SPK, sPQ = sb + AT_SPQ;
    const uint32_t sC = sb + AT_SC, sP = sb + AT_SP;

    const int tid = threadIdx.x, warp = tid >> 5, lane = tid & 31;
    const int g = lane >> 2, tg = lane & 3;
    const int matm = lane >> 3, rin = lane & 7;
    const int wm = warp * 16;
    const int i0 = blockIdx.x * 64;
    const int bh = blockIdx.y;
    const int h = bh & (H_ - 1);

    const __nv_bfloat16* qb  = q + ((size_t)bh * N_ + i0) * HD_;
    const __nv_bfloat16* kb  = k + (size_t)bh * N_ * HD_;
    const __nv_bfloat16* vb  = v + (size_t)bh * N_ * HD_;
    const __nv_bfloat16* pkb = posk + (size_t)h * TWO_PB * HD_;
    const __nv_bfloat16* pqb = posq + (size_t)h * TWO_PB * HD_;

    #pragma unroll
    for (int it = 0; it < 4; it++) {
        int c = it * 128 + tid, r = c >> 3, k8 = c & 7;
        CP_ASYNC16(sQ + SWZ((uint32_t)(r * 128 + k8 * 16)), qb + r * HD_ + k8 * 8);
    }
    CP_COMMIT();

    float m0 = -INFINITY, m1 = -INFINITY, l0 = 0.f, l1 = 0.f;
    float opv[8][4];
    #pragma unroll
    for (int i = 0; i < 8; i++)
        #pragma unroll
        for (int e = 0; e < 4; e++) opv[i][e] = 0.f;
    const float inv_scale = 0.0721687836f;     // 1/sqrt(192)

    for (int j0 = 0; j0 < N_; j0 += 64) {
        const int base = i0 - j0 + PB_ - 63;
        #pragma unroll
        for (int it = 0; it < 4; it++) {
            int c = it * 128 + tid, r = c >> 3, k8 = c & 7;
            uint32_t off = SWZ((uint32_t)(r * 128 + k8 * 16));
            CP_ASYNC16(sK + off, kb + (size_t)(j0 + r) * HD_ + k8 * 8);
            CP_ASYNC16(sV + off, vb + (size_t)(j0 + r) * HD_ + k8 * 8);
        }
        #pragma unroll
        for (int it = 0; it < 8; it++) {
            int c = it * 128 + tid, r = c >> 3, k8 = c & 7;
            int sr = base + r; if (sr > 1023) sr = 1023;
            uint32_t off = SWZ((uint32_t)(r * 128 + k8 * 16));
            CP_ASYNC16(sPK + off, pkb + (size_t)sr * HD_ + k8 * 8);
            CP_ASYNC16(sPQ + off, pqb + (size_t)sr * HD_ + k8 * 8);
        }
        CP_COMMIT(); CP_WAIT0(); __syncthreads();

        // phase 1: band GEMMs C2P = Q.PKwin^T, P2C = K.PQwin^T
        #pragma unroll
        for (int ph = 0; ph < 2; ph++) {
            uint32_t aSrc = ph ? sK : sQ;
            uint32_t bSrc = ph ? sPQ : sPK;
            uint32_t dSt  = ph ? sP : sC;
            float t[16][4];
            #pragma unroll
            for (int i = 0; i < 16; i++)
                #pragma unroll
                for (int e = 0; e < 4; e++) t[i][e] = 0.f;
            #pragma unroll
            for (int ks = 0; ks < 4; ks++) {
                uint32_t af[4];
                int ar = wm + (matm & 1) * 8 + rin, kc = ks * 16 + (matm >> 1) * 8;
                ldsm_x4(af, aSrc + SWZ((uint32_t)(ar * 128 + kc * 2)));
                #pragma unroll
                for (int u = 0; u < 8; u++) {
                    uint32_t bf4[4];
                    int nr = u * 16 + (matm & 1) * 8 + rin;
                    ldsm_x4(bf4, bSrc + SWZ((uint32_t)(nr * 128 + kc * 2)));
                    mma16816(t[2 * u],     af, bf4[0], bf4[2]);
                    mma16816(t[2 * u + 1], af, bf4[1], bf4[3]);
                }
            }
            #pragma unroll
            for (int nt = 0; nt < 16; nt++) {
                int col = nt * 8 + tg * 2;
                __nv_bfloat162 lo = __floats2bfloat162_rn(t[nt][0], t[nt][1]);
                __nv_bfloat162 hi = __floats2bfloat162_rn(t[nt][2], t[nt][3]);
                uint32_t a0 = dSt + (wm + g) * BAND_STRIDE + col * 2;
                uint32_t a1 = dSt + (wm + g + 8) * BAND_STRIDE + col * 2;
                asm volatile("st.shared.b32 [%0], %1;" :: "r"(a0), "r"(*(uint32_t*)&lo));
                asm volatile("st.shared.b32 [%0], %1;" :: "r"(a1), "r"(*(uint32_t*)&hi));
            }
        }
        __syncthreads();

        // phase 2: S = Q.K^T + band gather, online softmax
        float s[8][4];
        #pragma unroll
        for (int i = 0; i < 8; i++)
            #pragma unroll
            for (int e = 0; e < 4; e++) s[i][e] = 0.f;
        #pragma unroll
        for (int ks = 0; ks < 4; ks++) {
            uint32_t af[4];
            int ar = wm + (matm & 1) * 8 + rin, kc = ks * 16 + (matm >> 1) * 8;
            ldsm_x4(af, sQ + SWZ((uint32_t)(ar * 128 + kc * 2)));
            #pragma unroll
            for (int u = 0; u < 4; u++) {
                uint32_t bf4[4];
                int nr = u * 16 + (matm & 1) * 8 + rin;
                ldsm_x4(bf4, sK + SWZ((uint32_t)(nr * 128 + kc * 2)));
                mma16816(s[2 * u],     af, bf4[0], bf4[2]);
                mma16816(s[2 * u + 1], af, bf4[1], bf4[3]);
            }
        }
        #pragma unroll
        for (int nt = 0; nt < 8; nt++) {
            #pragma unroll
            for (int e = 0; e < 4; e++) {
                int di = wm + g + (e >> 1) * 8;
                int dj = nt * 8 + tg * 2 + (e & 1);
                int w = di - dj + 63;
                uint16_t cv, pv2;
                asm volatile("ld.shared.u16 %0, [%1];" : "=h"(cv)
                             : "r"(sC + di * BAND_STRIDE + w * 2));
                asm volatile("ld.shared.u16 %0, [%1];" : "=h"(pv2)
                             : "r"(sP + dj * BAND_STRIDE + w * 2));
                float add = __bfloat162float(*(__nv_bfloat16*)&cv)
                          + __bfloat162float(*(__nv_bfloat16*)&pv2);
                s[nt][e] = (s[nt][e] + add) * inv_scale;
            }
        }
        float mx0 = -INFINITY, mx1 = -INFINITY;
        #pragma unroll
        for (int nt = 0; nt < 8; nt++) {
            mx0 = fmaxf(mx0, fmaxf(s[nt][0], s[nt][1]));
            mx1 = fmaxf(mx1, fmaxf(s[nt][2], s[nt][3]));
        }
        mx0 = fmaxf(mx0, __shfl_xor_sync(0xFFFFFFFF, mx0, 1));
        mx0 = fmaxf(mx0, __shfl_xor_sync(0xFFFFFFFF, mx0, 2));
        mx1 = fmaxf(mx1, __shfl_xor_sync(0xFFFFFFFF, mx1, 1));
        mx1 = fmaxf(mx1, __shfl_xor_sync(0xFFFFFFFF, mx1, 2));
        float mn0 = fmaxf(m0, mx0), mn1 = fmaxf(m1, mx1);
        float sc0 = __expf(m0 - mn0), sc1 = __expf(m1 - mn1);
        m0 = mn0; m1 = mn1;
        float sum0 = 0.f, sum1 = 0.f;
        #pragma unroll
        for (int nt = 0; nt < 8; nt++) {
            #pragma unroll
            for (int e = 0; e < 4; e++) {
                float p = __expf(s[nt][e] - ((e < 2) ? mn0 : mn1));
                s[nt][e] = p;
                if (e < 2) sum0 += p; else sum1 += p;
            }
        }
        sum0 += __shfl_xor_sync(0xFFFFFFFF, sum0, 1);
        sum0 += __shfl_xor_sync(0xFFFFFFFF, sum0, 2);
        sum1 += __shfl_xor_sync(0xFFFFFFFF, sum1, 1);
        sum1 += __shfl_xor_sync(0xFFFFFFFF, sum1, 2);
        l0 = l0 * sc0 + sum0;
        l1 = l1 * sc1 + sum1;
        #pragma unroll
        for (int nt = 0; nt < 8; nt++) {
            opv[nt][0] *= sc0; opv[nt][1] *= sc0;
            opv[nt][2] *= sc1; opv[nt][3] *= sc1;
        }
        #pragma unroll
        for (int kk = 0; kk < 4; kk++) {
            uint32_t aP[4];
            __nv_bfloat162 t0 = __floats2bfloat162_rn(s[2*kk][0],   s[2*kk][1]);
            __nv_bfloat162 t1 = __floats2bfloat162_rn(s[2*kk][2],   s[2*kk][3]);
            __nv_bfloat162 t2 = __floats2bfloat162_rn(s[2*kk+1][0], s[2*kk+1][1]);
            __nv_bfloat162 t3 = __floats2bfloat162_rn(s[2*kk+1][2], s[2*kk+1][3]);
            aP[0] = *(uint32_t*)&t0; aP[1] = *(uint32_t*)&t1;
            aP[2] = *(uint32_t*)&t2; aP[3] = *(uint32_t*)&t3;
            int jb = kk * 16;
            #pragma unroll
            for (int du = 0; du < 4; du++) {
                uint32_t bv[4];
                int vr = jb + (matm & 1) * 8 + rin, vc = du * 16 + (matm >> 1) * 8;
                ldsm_x4_t(bv, sV + SWZ((uint32_t)(vr * 128 + vc * 2)));
                mma16816(opv[2 * du],     aP, bv[0], bv[1]);
                mma16816(opv[2 * du + 1], aP, bv[2], bv[3]);
            }
        }
        __syncthreads();
    }

    const int b = bh >> 4;
    float il0 = 1.0f / l0, il1 = 1.0f / l1;
    int row0 = i0 + wm + g, row1 = row0 + 8;
    #pragma unroll
    for (int nt = 0; nt < 8; nt++) {
        int d = nt * 8 + tg * 2;
        __nv_bfloat162 o0 = __floats2bfloat162_rn(opv[nt][0] * il0, opv[nt][1] * il0);
        __nv_bfloat162 o1 = __floats2bfloat162_rn(opv[nt][2] * il1, opv[nt][3] * il1);
        *(__nv_bfloat162*)&ctx[(((size_t)b * N_ + row0) * H_ + h) * HD_ + d] = o0;
        *(__nv_bfloat162*)&ctx[(((size_t)b * N_ + row1) * H_ + h) * HD_ + d] = o1;
    }
}

// ---------------------------------------------------------------------------
// Row LayerNorm
// ---------------------------------------------------------------------------
__global__ __launch_bounds__(256) void ln_kernel(
    const float* __restrict__ hb, const float* __restrict__ gam,
    const float* __restrict__ bet, float* __restrict__ out)
{
    const int row = blockIdx.x, tid = threadIdx.x;
    const float* hr = hb + (size_t)row * D_;
    __shared__ float red[256];

    float lv[4];
    float s = 0.0f;
    #pragma unroll
    for (int i = 0; i < 4; i++) { lv[i] = hr[i*256 + tid]; s += lv[i]; }
    red[tid] = s; __syncthreads();
    #pragma unroll
    for (int o = 128; o > 0; o >>= 1) { if (tid < o) red[tid] += red[tid + o]; __syncthreads(); }
    float mu = red[0] * (1.0f / 1024.0f);
    __syncthreads();

    float s2 = 0.0f;
    #pragma unroll
    for (int i = 0; i < 4; i++) { float dv = lv[i] - mu; s2 += dv * dv; }
    red[tid] = s2; __syncthreads();
    #pragma unroll
    for (int o = 128; o > 0; o >>= 1) { if (tid < o) red[tid] += red[tid + o]; __syncthreads(); }
    float var = red[0] * (1.0f / 1024.0f);
    float inv = rsqrtf(var + 1e-7f);

    #pragma unroll
    for (int i = 0; i < 4; i++) {
        int c = i*256 + tid;
        out[(size_t)row * D_ + c] = (lv[i] - mu) * inv * gam[c] + bet[c];
    }
}

// ---------------------------------------------------------------------------
extern "C" void kernel_launch(void* const* d_in, const int* in_sizes, int n_in,
                              void* d_out, int out_size)
{
    const float* hidden = (const float*)d_in[0];
    const float* rel    = (const float*)d_in[1];
    const float* q_w = (const float*)d_in[2];  const float* q_b = (const float*)d_in[3];
    const float* k_w = (const float*)d_in[4];  const float* k_b = (const float*)d_in[5];
    const float* v_w = (const float*)d_in[6];  const float* v_b = (const float*)d_in[7];
    const float* pk_w = (const float*)d_in[8]; const float* pk_b = (const float*)d_in[9];
    const float* pq_w = (const float*)d_in[10];const float* pq_b = (const float*)d_in[11];
    const float* o_w = (const float*)d_in[12]; const float* o_b = (const float*)d_in[13];
    const float* ln_g = (const float*)d_in[14];const float* ln_b = (const float*)d_in[15];

    __nv_bfloat16 *pqb, *pkb, *pvb, *ppk, *ppq, *pctxbf, *phidbf, *prelbf, *pwbf;
    float *ph;
    cudaGetSymbolAddress((void**)&pqb,  g_qb);
    cudaGetSymbolAddress((void**)&pkb,  g_kb);
    cudaGetSymbolAddress((void**)&pvb,  g_vb);
    cudaGetSymbolAddress((void**)&ppk,  g_pkb);
    cudaGetSymbolAddress((void**)&ppq,  g_pqb);
    cudaGetSymbolAddress((void**)&pctxbf, g_ctx_bf);
    cudaGetSymbolAddress((void**)&ph,   g_h);
    cudaGetSymbolAddress((void**)&phidbf, g_hid_bf);
    cudaGetSymbolAddress((void**)&prelbf, g_rel_bf);
    cudaGetSymbolAddress((void**)&pwbf,   g_wbf);

    __nv_bfloat16* wq  = pwbf + 0ull * D_ * D_;   // QKV fused base
    __nv_bfloat16* wpk = pwbf + 3ull * D_ * D_;   // pos fused base
    __nv_bfloat16* wo  = pwbf + 5ull * D_ * D_;

    cudaFuncSetAttribute(gemm_mma, cudaFuncAttributeMaxDynamicSharedMemorySize, GEMM_SMEM);
    cudaFuncSetAttribute(attn_mma, cudaFuncAttributeMaxDynamicSharedMemorySize, AT_SMEM);

    // fp32 -> bf16 conversions
    f2bf<<<BN_*D_/1024, 256>>>(hidden, phidbf, BN_*D_);
    f2bf<<<TWO_PB*D_/1024, 256>>>(rel, prelbf, TWO_PB*D_);
    f2bf6<<<dim3(D_*D_/1024, 6), 256>>>(q_w, k_w, v_w, pk_w, pq_w, o_w, pwbf);

    // fused QKV projection: one launch, N=3072
    gemm_mma<<<dim3(3*D_/128, BN_/128), 256, GEMM_SMEM>>>(
        phidbf, wq, q_b, k_b, v_b, nullptr, nullptr, 1);
    // fused pos projections: one launch, N=2048
    gemm_mma<<<dim3(2*D_/128, TWO_PB/128), 256, GEMM_SMEM>>>(
        prelbf, wpk, pk_b, pq_b, nullptr, nullptr, nullptr, 0);

    // tensorized disentangled flash attention -> bf16 ctx
    attn_mma<<<dim3(N_/64, B_*H_), 128, AT_SMEM>>>(pqb, pkb, pvb, ppk, ppq, pctxbf);

    // output projection + bias + residual (fp32 out)
    gemm_mma<<<dim3(D_/128, BN_/128), 256, GEMM_SMEM>>>(
        pctxbf, wo, o_b, o_b, o_b, hidden, ph, 2);

    // layernorm -> final output
    ln_kernel<<<BN_, 256>>>(ph, ln_g, ln_b, (float*)d_out);
}